// round 5
// baseline (speedup 1.0000x reference)
#include <cuda_runtime.h>
#include <math.h>

#define BTOT   65536
#define INS    360
#define L1N    180
#define NPOS   90
#define TS     32
#define KIN    33
#define HID    24
#define SAMP   8       // samples per block (1 per warp)
#define THREADS 256

// ---- shared memory layout (float offsets) ----
#define OFF_W1F   0                       // 6*5 folded conv1 w
#define OFF_B1F   (OFF_W1F + 30)          // 6
#define OFF_W2F   (OFF_B1F + 6)           // 12*6*3 folded conv2 w
#define OFF_B2F   (OFF_W2F + 216)         // 12
#define OFF_WIH   264                     // 96 rows, swizzled stride
#define WIH_SZ    (96*36 + 48)
#define OFF_WHH   (OFF_WIH + 3504)        // 264+3504 = 3768
#define WHH_SZ    (96*28 + 48)
#define OFF_BSUM  (OFF_WHH + 2736)        // 6504
#define OFF_RTW1  (OFF_BSUM + 96)         // 6600
#define OFF_RTB1  (OFF_RTW1 + 432)        // 7032
#define OFF_RTW2  (OFF_RTB1 + 12)         // 7044
#define OFF_RTB2  (OFF_RTW2 + 24)         // 7068
#define OFF_FUSW  (OFF_RTB2 + 4)          // 7072
#define OFF_FUSB  (OFF_FUSW + 864)        // 7936
#define OFF_CW1   (OFF_FUSB + 24)         // 7960
#define OFF_CB1   (OFF_CW1 + 288)         // 8248
#define OFF_CW2   (OFF_CB1 + 12)          // 8260
#define OFF_CB2   (OFF_CW2 + 60)          // 8320
#define OFF_CONV  8328                    // 8 samples * 32 t * 36 (16B aligned)
#define OFF_H     (OFF_CONV + SAMP*32*36) // 17544, 8 * 24
#define OFF_G     (OFF_H + SAMP*24)       // 17736, 8 * 96
#define OFF_SA    (OFF_G + SAMP*96)       // 18504, 8 * 12
#define SMEM_FLOATS (OFF_SA + SAMP*12)    // 18600
#define SMEM_BYTES  (SMEM_FLOATS * 4)     // 74400

// bank-swizzled row starts (conflict-free per-lane row reads)
__device__ __forceinline__ int WIH_ROW(int r) { return r * 36 + ((r >> 3) << 2); }
__device__ __forceinline__ int WHH_ROW(int r) { return r * 28 + ((r >> 3) << 2); }

__device__ __forceinline__ float sigf(float x) {
    return __fdividef(1.0f, 1.0f + __expf(-x));
}
__device__ __forceinline__ float tanhfast(float x) {
    return fmaf(2.0f, __fdividef(1.0f, 1.0f + __expf(-2.0f * x)), -1.0f);
}

__global__ __launch_bounds__(THREADS) void fused_kernel(
    const float* __restrict__ x,
    const float* __restrict__ c1w, const float* __restrict__ c1b,
    const float* __restrict__ bn1g, const float* __restrict__ bn1b,
    const float* __restrict__ bn1m, const float* __restrict__ bn1v,
    const float* __restrict__ c2w, const float* __restrict__ c2b,
    const float* __restrict__ bn2g, const float* __restrict__ bn2b,
    const float* __restrict__ bn2m, const float* __restrict__ bn2v,
    const float* __restrict__ wih, const float* __restrict__ whh,
    const float* __restrict__ bih, const float* __restrict__ bhh,
    const float* __restrict__ rtw1, const float* __restrict__ rtb1,
    const float* __restrict__ rtw2, const float* __restrict__ rtb2,
    const float* __restrict__ fusw, const float* __restrict__ fusb,
    const float* __restrict__ cw1, const float* __restrict__ cb1,
    const float* __restrict__ cw2, const float* __restrict__ cb2,
    float* __restrict__ out)
{
    extern __shared__ float sm[];
    const int tid  = threadIdx.x;
    const int wid  = tid >> 5;
    const int lane = tid & 31;

    // ---------------- cooperative weight load + BN fold ----------------
    if (tid < 6) {
        float sc = bn1g[tid] * rsqrtf(bn1v[tid] + 1e-5f);
        #pragma unroll
        for (int r = 0; r < 5; r++) sm[OFF_W1F + tid * 5 + r] = c1w[tid * 5 + r] * sc;
        sm[OFF_B1F + tid] = (c1b[tid] - bn1m[tid]) * sc + bn1b[tid];
    } else if (tid >= 32 && tid < 44) {
        int co = tid - 32;
        float sc = bn2g[co] * rsqrtf(bn2v[co] + 1e-5f);
        #pragma unroll
        for (int i = 0; i < 18; i++) sm[OFF_W2F + co * 18 + i] = c2w[co * 18 + i] * sc;
        sm[OFF_B2F + co] = (c2b[co] - bn2m[co]) * sc + bn2b[co];
    }
    for (int i = tid; i < 96 * 33; i += THREADS) {
        int r = i / 33, k = i - r * 33;
        sm[OFF_WIH + WIH_ROW(r) + k] = wih[i];
    }
    for (int i = tid; i < 96 * 24; i += THREADS) {
        int r = i / 24, k = i - r * 24;
        sm[OFF_WHH + WHH_ROW(r) + k] = whh[i];
    }
    if (tid < 96) sm[OFF_BSUM + tid] = bih[tid] + bhh[tid];
    for (int i = tid; i < 432; i += THREADS) sm[OFF_RTW1 + i] = rtw1[i];
    for (int i = tid; i < 864; i += THREADS) sm[OFF_FUSW + i] = fusw[i];
    for (int i = tid; i < 288; i += THREADS) sm[OFF_CW1 + i] = cw1[i];
    if (tid < 12) sm[OFF_RTB1 + tid] = rtb1[tid];
    if (tid < 24) sm[OFF_RTW2 + tid] = rtw2[tid];
    if (tid < 2)  sm[OFF_RTB2 + tid] = rtb2[tid];
    if (tid < 24) sm[OFF_FUSB + tid] = fusb[tid];
    if (tid < 12) sm[OFF_CB1 + tid] = cb1[tid];
    if (tid < 60) sm[OFF_CW2 + tid] = cw2[tid];
    if (tid < 5)  sm[OFF_CB2 + tid] = cb2[tid];
    __syncthreads();

    // ---------------- per-warp: one sample ----------------
    const int sg = blockIdx.x * SAMP + wid;        // global sample
    const float* xr = x + (size_t)sg * INS;
    float* conv = sm + OFF_CONV + wid * 32 * 36;   // [t][k] padded to 36
    float* h_s  = sm + OFF_H + wid * 24;
    float* g_s  = sm + OFF_G + wid * 96;
    float* sa_s = sm + OFF_SA + wid * 12;

    if (lane < 12) sa_s[lane] = 0.0f;
    __syncwarp();

    // -------- conv1+conv2 (BN folded, ReLU), write [t][k], spatial sum --------
    float sacc[12];
    #pragma unroll
    for (int co = 0; co < 12; co++) sacc[co] = 0.0f;

    for (int p = lane; p < NPOS; p += 32) {
        float c1v[3][6];
        #pragma unroll
        for (int dq = 0; dq < 3; dq++) {
            int q = 2 * p - 1 + dq;
            if (q >= 0 && q < L1N) {
                int base = 2 * q - 2;
                #pragma unroll
                for (int ci = 0; ci < 6; ci++) {
                    float acc = sm[OFF_B1F + ci];
                    #pragma unroll
                    for (int r = 0; r < 5; r++) {
                        int idx = base + r;
                        if (idx >= 0 && idx < INS)
                            acc = fmaf(sm[OFF_W1F + ci * 5 + r], xr[idx], acc);
                    }
                    c1v[dq][ci] = fmaxf(acc, 0.0f);
                }
            } else {
                #pragma unroll
                for (int ci = 0; ci < 6; ci++) c1v[dq][ci] = 0.0f;
            }
        }
        int f0 = p * 12;
        int t  = f0 / 33;
        int k  = f0 - t * 33;
        bool store = (p < 88);
        #pragma unroll
        for (int co = 0; co < 12; co++) {
            float acc = sm[OFF_B2F + co];
            #pragma unroll
            for (int dq = 0; dq < 3; dq++)
                #pragma unroll
                for (int ci = 0; ci < 6; ci++)
                    acc = fmaf(sm[OFF_W2F + (co * 6 + ci) * 3 + dq], c1v[dq][ci], acc);
            float v = fmaxf(acc, 0.0f);
            sacc[co] += v;
            if (store) conv[t * 36 + k] = v;
            if (++k == 33) { k = 0; ++t; }
        }
    }
    #pragma unroll
    for (int co = 0; co < 12; co++) atomicAdd(&sa_s[co], sacc[co]);
    __syncwarp();
    if (lane < 12) sa_s[lane] *= (1.0f / 90.0f);
    __syncwarp();

    // -------- LIF x2 (lane = k; lane 0 also k=32), overwrite conv with spikes --------
    {
        float m1a = 0.0f, m2a = 0.0f, m1b = 0.0f, m2b = 0.0f;
        #pragma unroll 1
        for (int t = 0; t < TS; t++) {
            float* row = conv + t * 36;
            float xv = row[lane];
            float m1 = fmaf(0.95f, m1a, xv);
            bool f1 = (m1 > 0.5f);
            m1a = f1 ? 0.0f : m1;
            float m2 = fmaf(0.9f, m2a, f1 ? 1.0f : 0.0f);
            bool f2 = (m2 > 0.6f);
            m2a = f2 ? 0.0f : m2;
            row[lane] = f2 ? 1.0f : 0.0f;
            if (lane == 0) {
                float xb = row[32];
                float n1 = fmaf(0.95f, m1b, xb);
                bool g1 = (n1 > 0.5f);
                m1b = g1 ? 0.0f : n1;
                float n2 = fmaf(0.9f, m2b, g1 ? 1.0f : 0.0f);
                bool g2 = (n2 > 0.6f);
                m2b = g2 ? 0.0f : n2;
                row[32] = g2 ? 1.0f : 0.0f;
            }
        }
    }
    if (lane < 24) h_s[lane] = 0.0f;
    __syncwarp();

    // -------- LSTM: 96 gate rows / 32 lanes = 3 rows each --------
    float c_u = 0.0f;
    #pragma unroll 1
    for (int t = 0; t < TS; t++) {
        const float* sp = conv + t * 36;
        // hoist broadcasts
        float4 s4[8];
        #pragma unroll
        for (int i = 0; i < 8; i++) s4[i] = ((const float4*)sp)[i];
        float sp32 = sp[32];
        float4 h4[6];
        #pragma unroll
        for (int i = 0; i < 6; i++) h4[i] = ((const float4*)h_s)[i];

        #pragma unroll
        for (int rr3 = 0; rr3 < 3; rr3++) {
            int rr = lane + rr3 * 32;
            float g = sm[OFF_BSUM + rr];
            const float4* w4 = (const float4*)(sm + OFF_WIH + WIH_ROW(rr));
            #pragma unroll
            for (int i = 0; i < 8; i++) {
                float4 a = w4[i], b = s4[i];
                g = fmaf(a.x, b.x, g); g = fmaf(a.y, b.y, g);
                g = fmaf(a.z, b.z, g); g = fmaf(a.w, b.w, g);
            }
            g = fmaf((sm + OFF_WIH + WIH_ROW(rr))[32], sp32, g);
            const float4* v4 = (const float4*)(sm + OFF_WHH + WHH_ROW(rr));
            #pragma unroll
            for (int i = 0; i < 6; i++) {
                float4 a = v4[i], b = h4[i];
                g = fmaf(a.x, b.x, g); g = fmaf(a.y, b.y, g);
                g = fmaf(a.z, b.z, g); g = fmaf(a.w, b.w, g);
            }
            g_s[rr] = g;
        }
        __syncwarp();
        if (lane < 24) {
            float gi = g_s[lane], gf = g_s[24 + lane], gg = g_s[48 + lane], go = g_s[72 + lane];
            c_u = fmaf(sigf(gf), c_u, sigf(gi) * tanhfast(gg));
            h_s[lane] = sigf(go) * tanhfast(c_u);
        }
        __syncwarp();
    }

    // ---------------- head (lane-parallel within warp) ----------------
    // a1 (12) -> g_s[36..47]
    if (lane < 12) {
        float acc = sm[OFF_RTB1 + lane];
        #pragma unroll
        for (int j = 0; j < 24; j++) acc = fmaf(sm[OFF_RTW1 + lane * 36 + j], h_s[j], acc);
        #pragma unroll
        for (int j = 0; j < 12; j++) acc = fmaf(sm[OFF_RTW1 + lane * 36 + 24 + j], sa_s[j], acc);
        g_s[36 + lane] = fmaxf(acc, 0.0f);
    }
    __syncwarp();
    if (lane == 0) {
        float l0 = sm[OFF_RTB2 + 0], l1 = sm[OFF_RTB2 + 1];
        #pragma unroll
        for (int j = 0; j < 12; j++) {
            float a = g_s[36 + j];
            l0 = fmaf(sm[OFF_RTW2 + j], a, l0);
            l1 = fmaf(sm[OFF_RTW2 + 12 + j], a, l1);
        }
        float mx = fmaxf(l0, l1);
        float e0 = __expf(l0 - mx), e1 = __expf(l1 - mx);
        float inv = 1.0f / (e0 + e1);
        float r0 = 0.7f * e0 * inv, r1 = 0.3f * e1 * inv;
        g_s[48] = r0 / (r0 + r1);                // alpha
    }
    __syncwarp();
    float alpha = g_s[48];
    float beta  = 1.0f - alpha;
    // fused (24) -> g_s[0..23]  (g_s gate slots dead now; a1 at 36.. kept until read done)
    if (lane < 24) {
        float acc = sm[OFF_FUSB + lane];
        #pragma unroll
        for (int j = 0; j < 24; j++) acc = fmaf(sm[OFF_FUSW + lane * 36 + j], h_s[j] * alpha, acc);
        #pragma unroll
        for (int j = 0; j < 12; j++) acc = fmaf(sm[OFF_FUSW + lane * 36 + 24 + j], sa_s[j] * beta, acc);
        g_s[lane] = fmaxf(acc, 0.0f);
    }
    __syncwarp();
    // z (12) -> g_s[64..75]
    if (lane < 12) {
        float acc = sm[OFF_CB1 + lane];
        #pragma unroll
        for (int o = 0; o < 24; o++) acc = fmaf(sm[OFF_CW1 + lane * 24 + o], g_s[o], acc);
        g_s[64 + lane] = fmaxf(acc, 0.0f);
    }
    __syncwarp();
    if (lane < 5) {
        float acc = sm[OFF_CB2 + lane];
        #pragma unroll
        for (int i = 0; i < 12; i++) acc = fmaf(sm[OFF_CW2 + lane * 12 + i], g_s[64 + i], acc);
        out[(size_t)sg * 5 + lane] = acc;
    }
}

// =====================================================================
extern "C" void kernel_launch(void* const* d_in, const int* in_sizes, int n_in,
                              void* d_out, int out_size) {
    (void)in_sizes; (void)n_in; (void)out_size;
    cudaFuncSetAttribute(fused_kernel,
                         cudaFuncAttributeMaxDynamicSharedMemorySize, SMEM_BYTES);
    fused_kernel<<<BTOT / SAMP, THREADS, SMEM_BYTES>>>(
        (const float*)d_in[0],
        (const float*)d_in[1],  (const float*)d_in[2],
        (const float*)d_in[3],  (const float*)d_in[4],
        (const float*)d_in[5],  (const float*)d_in[6],
        (const float*)d_in[7],  (const float*)d_in[8],
        (const float*)d_in[9],  (const float*)d_in[10],
        (const float*)d_in[11], (const float*)d_in[12],
        (const float*)d_in[13], (const float*)d_in[14],
        (const float*)d_in[15], (const float*)d_in[16],
        (const float*)d_in[17], (const float*)d_in[18],
        (const float*)d_in[19], (const float*)d_in[20],
        (const float*)d_in[21], (const float*)d_in[22],
        (const float*)d_in[23], (const float*)d_in[24],
        (const float*)d_in[25], (const float*)d_in[26],
        (float*)d_out);
}

// round 6
// speedup vs baseline: 1.0976x; 1.0976x over previous
#include <cuda_runtime.h>
#include <math.h>

#define BTOT   65536
#define INS    360
#define L1N    180
#define NPOS   90
#define TS     32
#define KIN    33
#define HID    24
#define SAMP   8
#define THREADS 256

// ---- shared memory layout (float offsets) ----
#define OFF_W1F   0
#define OFF_B1F   30
#define OFF_W2F   36
#define OFF_B2F   252
#define OFF_WIH   264                 // 96 rows, stride 36 + swizzle (3504)
#define OFF_WHH   3768                // 96 rows, stride 36 + swizzle (3504)
#define OFF_BSUM  7272
#define OFF_RTW1  7368
#define OFF_RTB1  7800
#define OFF_RTW2  7812
#define OFF_RTB2  7836
#define OFF_FUSW  7840
#define OFF_FUSB  8704
#define OFF_CW1   8728
#define OFF_CB1   9016
#define OFF_CW2   9028
#define OFF_CB2   9088
#define OFF_CONV  9096                // 8 samples * CSTR
#define CSTR      1156                // 32*36 + 4 pad  (mod 32 == 4)
#define OFF_H     (OFF_CONV + SAMP*CSTR)   // 18344, stride 28/sample
#define OFF_G     (OFF_H + SAMP*28)        // 18568, stride 100/sample
#define OFF_SA    (OFF_G + SAMP*100)       // 19368
#define SMEM_FLOATS (OFF_SA + SAMP*12)     // 19464
#define SMEM_BYTES  (SMEM_FLOATS * 4)      // 77856

// swizzled row start: stride 36, +4 banks per 8 rows -> 4 consecutive-ish rows
// and 8-sample activation groups are bank-disjoint
__device__ __forceinline__ int WROW(int r) { return r * 36 + ((r >> 3) << 2); }

__device__ __forceinline__ float sigf(float x) {
    return __fdividef(1.0f, 1.0f + __expf(-x));
}
__device__ __forceinline__ float tanhfast(float x) {
    return fmaf(2.0f, __fdividef(1.0f, 1.0f + __expf(-2.0f * x)), -1.0f);
}

__global__ __launch_bounds__(THREADS, 2) void fused_kernel(
    const float* __restrict__ x,
    const float* __restrict__ c1w, const float* __restrict__ c1b,
    const float* __restrict__ bn1g, const float* __restrict__ bn1b,
    const float* __restrict__ bn1m, const float* __restrict__ bn1v,
    const float* __restrict__ c2w, const float* __restrict__ c2b,
    const float* __restrict__ bn2g, const float* __restrict__ bn2b,
    const float* __restrict__ bn2m, const float* __restrict__ bn2v,
    const float* __restrict__ wih, const float* __restrict__ whh,
    const float* __restrict__ bih, const float* __restrict__ bhh,
    const float* __restrict__ rtw1, const float* __restrict__ rtb1,
    const float* __restrict__ rtw2, const float* __restrict__ rtb2,
    const float* __restrict__ fusw, const float* __restrict__ fusb,
    const float* __restrict__ cw1, const float* __restrict__ cb1,
    const float* __restrict__ cw2, const float* __restrict__ cb2,
    float* __restrict__ out)
{
    extern __shared__ float sm[];
    const int tid  = threadIdx.x;
    const int wid  = tid >> 5;
    const int lane = tid & 31;

    // ---------------- cooperative weight load + BN fold ----------------
    if (tid < 6) {
        float sc = bn1g[tid] * rsqrtf(bn1v[tid] + 1e-5f);
        #pragma unroll
        for (int r = 0; r < 5; r++) sm[OFF_W1F + tid * 5 + r] = c1w[tid * 5 + r] * sc;
        sm[OFF_B1F + tid] = (c1b[tid] - bn1m[tid]) * sc + bn1b[tid];
    } else if (tid >= 32 && tid < 44) {
        int co = tid - 32;
        float sc = bn2g[co] * rsqrtf(bn2v[co] + 1e-5f);
        #pragma unroll
        for (int i = 0; i < 18; i++) sm[OFF_W2F + co * 18 + i] = c2w[co * 18 + i] * sc;
        sm[OFF_B2F + co] = (c2b[co] - bn2m[co]) * sc + bn2b[co];
    }
    for (int i = tid; i < 96 * 33; i += THREADS) {
        int r = i / 33, k = i - r * 33;
        sm[OFF_WIH + WROW(r) + k] = wih[i];
    }
    for (int i = tid; i < 96 * 24; i += THREADS) {
        int r = i / 24, k = i - r * 24;
        sm[OFF_WHH + WROW(r) + k] = whh[i];
    }
    if (tid < 96) sm[OFF_BSUM + tid] = bih[tid] + bhh[tid];
    for (int i = tid; i < 432; i += THREADS) sm[OFF_RTW1 + i] = rtw1[i];
    for (int i = tid; i < 864; i += THREADS) sm[OFF_FUSW + i] = fusw[i];
    for (int i = tid; i < 288; i += THREADS) sm[OFF_CW1 + i] = cw1[i];
    if (tid < 12) sm[OFF_RTB1 + tid] = rtb1[tid];
    if (tid < 24) sm[OFF_RTW2 + tid] = rtw2[tid];
    if (tid < 2)  sm[OFF_RTB2 + tid] = rtb2[tid];
    if (tid < 24) sm[OFF_FUSB + tid] = fusb[tid];
    if (tid < 12) sm[OFF_CB1 + tid] = cb1[tid];
    if (tid < 60) sm[OFF_CW2 + tid] = cw2[tid];
    if (tid < 5)  sm[OFF_CB2 + tid] = cb2[tid];
    __syncthreads();

    // ---------------- conv phase: warp = sample ----------------
    const int sg = blockIdx.x * SAMP + wid;
    const float* xr = x + (size_t)sg * INS;
    float* conv = sm + OFF_CONV + wid * CSTR;
    float* sa_s = sm + OFF_SA + wid * 12;

    if (lane < 12) sa_s[lane] = 0.0f;
    __syncwarp();

    float sacc[12];
    #pragma unroll
    for (int co = 0; co < 12; co++) sacc[co] = 0.0f;

    for (int p = lane; p < NPOS; p += 32) {
        float c1v[3][6];
        #pragma unroll
        for (int dq = 0; dq < 3; dq++) {
            int q = 2 * p - 1 + dq;
            if (q >= 0 && q < L1N) {
                int base = 2 * q - 2;
                #pragma unroll
                for (int ci = 0; ci < 6; ci++) {
                    float acc = sm[OFF_B1F + ci];
                    #pragma unroll
                    for (int r = 0; r < 5; r++) {
                        int idx = base + r;
                        if (idx >= 0 && idx < INS)
                            acc = fmaf(sm[OFF_W1F + ci * 5 + r], xr[idx], acc);
                    }
                    c1v[dq][ci] = fmaxf(acc, 0.0f);
                }
            } else {
                #pragma unroll
                for (int ci = 0; ci < 6; ci++) c1v[dq][ci] = 0.0f;
            }
        }
        int f0 = p * 12;
        int t  = f0 / 33;
        int k  = f0 - t * 33;
        bool store = (p < 88);
        #pragma unroll
        for (int co = 0; co < 12; co++) {
            float acc = sm[OFF_B2F + co];
            #pragma unroll
            for (int dq = 0; dq < 3; dq++)
                #pragma unroll
                for (int ci = 0; ci < 6; ci++)
                    acc = fmaf(sm[OFF_W2F + (co * 6 + ci) * 3 + dq], c1v[dq][ci], acc);
            float v = fmaxf(acc, 0.0f);
            sacc[co] += v;
            if (store) conv[t * 36 + k] = v;
            if (++k == 33) { k = 0; ++t; }
        }
    }
    #pragma unroll
    for (int co = 0; co < 12; co++) atomicAdd(&sa_s[co], sacc[co]);
    __syncwarp();
    if (lane < 12) sa_s[lane] *= (1.0f / 90.0f);

    // ---------------- LIF phase: warp = sample, lane = k ----------------
    {
        float m1a = 0.0f, m2a = 0.0f, m1b = 0.0f, m2b = 0.0f;
        #pragma unroll 1
        for (int t = 0; t < TS; t++) {
            float* row = conv + t * 36;
            float xv = row[lane];
            float m1 = fmaf(0.95f, m1a, xv);
            bool f1 = (m1 > 0.5f);
            m1a = f1 ? 0.0f : m1;
            float m2 = fmaf(0.9f, m2a, f1 ? 1.0f : 0.0f);
            bool f2 = (m2 > 0.6f);
            m2a = f2 ? 0.0f : m2;
            row[lane] = f2 ? 1.0f : 0.0f;
            if (lane == 0) {
                float xb = row[32];
                float n1 = fmaf(0.95f, m1b, xb);
                bool g1 = (n1 > 0.5f);
                m1b = g1 ? 0.0f : n1;
                float n2 = fmaf(0.9f, m2b, g1 ? 1.0f : 0.0f);
                bool g2 = (n2 > 0.6f);
                m2b = g2 ? 0.0f : n2;
                row[32] = g2 ? 1.0f : 0.0f;
            }
        }
    }
    float* h_w = sm + OFF_H + wid * 28;
    float* g_w = sm + OFF_G + wid * 100;
    if (lane < 24) h_w[lane] = 0.0f;
    __syncthreads();   // spikes + h visible to all warps

    // ---------------- LSTM phase: block cooperates on all 8 samples ----------------
    // task (s = tid&7, rows rbase + 32p): weight row shared by 8 lanes (dedup),
    // activations conflict-free across 8 samples via CSTR/28 strides.
    const int s_idx = tid & 7;
    const int rbase = tid >> 3;          // 0..31
    const float* wp0 = sm + OFF_WIH + WROW(rbase);
    const float* wp1 = sm + OFF_WIH + WROW(rbase + 32);
    const float* wp2 = sm + OFF_WIH + WROW(rbase + 64);
    const float* vp0 = sm + OFF_WHH + WROW(rbase);
    const float* vp1 = sm + OFF_WHH + WROW(rbase + 32);
    const float* vp2 = sm + OFF_WHH + WROW(rbase + 64);
    const float  bb0 = sm[OFF_BSUM + rbase];
    const float  bb1 = sm[OFF_BSUM + rbase + 32];
    const float  bb2 = sm[OFF_BSUM + rbase + 64];
    const float* spbase = sm + OFF_CONV + s_idx * CSTR;
    const float* hrow   = sm + OFF_H + s_idx * 28;
    float* gout = sm + OFF_G + s_idx * 100 + rbase;

    float c_u = 0.0f;

    #pragma unroll 1
    for (int t = 0; t < TS; t++) {
        const float* sp = spbase + t * 36;
        float4 s4[8];
        #pragma unroll
        for (int i = 0; i < 8; i++) s4[i] = ((const float4*)sp)[i];
        float sp32 = sp[32];
        float4 h4[6];
        #pragma unroll
        for (int i = 0; i < 6; i++) h4[i] = ((const float4*)hrow)[i];

        {
            const float* wp[3] = {wp0, wp1, wp2};
            const float* vp[3] = {vp0, vp1, vp2};
            const float  bb[3] = {bb0, bb1, bb2};
            #pragma unroll
            for (int p = 0; p < 3; p++) {
                const float4* w4 = (const float4*)wp[p];
                float a0 = bb[p], a1 = 0.0f;
                #pragma unroll
                for (int i = 0; i < 8; i += 2) {
                    float4 wa = w4[i],     ba = s4[i];
                    float4 wb = w4[i + 1], bbv = s4[i + 1];
                    a0 = fmaf(wa.x, ba.x, a0); a0 = fmaf(wa.y, ba.y, a0);
                    a0 = fmaf(wa.z, ba.z, a0); a0 = fmaf(wa.w, ba.w, a0);
                    a1 = fmaf(wb.x, bbv.x, a1); a1 = fmaf(wb.y, bbv.y, a1);
                    a1 = fmaf(wb.z, bbv.z, a1); a1 = fmaf(wb.w, bbv.w, a1);
                }
                a0 = fmaf(wp[p][32], sp32, a0);
                const float4* v4 = (const float4*)vp[p];
                #pragma unroll
                for (int i = 0; i < 6; i += 2) {
                    float4 wa = v4[i],     ba = h4[i];
                    float4 wb = v4[i + 1], bbv = h4[i + 1];
                    a0 = fmaf(wa.x, ba.x, a0); a0 = fmaf(wa.y, ba.y, a0);
                    a0 = fmaf(wa.z, ba.z, a0); a0 = fmaf(wa.w, ba.w, a0);
                    a1 = fmaf(wb.x, bbv.x, a1); a1 = fmaf(wb.y, bbv.y, a1);
                    a1 = fmaf(wb.z, bbv.z, a1); a1 = fmaf(wb.w, bbv.w, a1);
                }
                gout[32 * p] = a0 + a1;
            }
        }
        __syncthreads();
        if (lane < 24) {
            float gi = g_w[lane], gf = g_w[24 + lane];
            float gg = g_w[48 + lane], go = g_w[72 + lane];
            c_u = fmaf(sigf(gf), c_u, sigf(gi) * tanhfast(gg));
            h_w[lane] = sigf(go) * tanhfast(c_u);
        }
        __syncthreads();
    }

    // ---------------- head (warp = sample) ----------------
    if (lane < 12) {
        float acc = sm[OFF_RTB1 + lane];
        #pragma unroll
        for (int j = 0; j < 24; j++) acc = fmaf(sm[OFF_RTW1 + lane * 36 + j], h_w[j], acc);
        #pragma unroll
        for (int j = 0; j < 12; j++) acc = fmaf(sm[OFF_RTW1 + lane * 36 + 24 + j], sa_s[j], acc);
        g_w[36 + lane] = fmaxf(acc, 0.0f);
    }
    __syncwarp();
    if (lane == 0) {
        float l0 = sm[OFF_RTB2 + 0], l1 = sm[OFF_RTB2 + 1];
        #pragma unroll
        for (int j = 0; j < 12; j++) {
            float a = g_w[36 + j];
            l0 = fmaf(sm[OFF_RTW2 + j], a, l0);
            l1 = fmaf(sm[OFF_RTW2 + 12 + j], a, l1);
        }
        float mx = fmaxf(l0, l1);
        float e0 = __expf(l0 - mx), e1 = __expf(l1 - mx);
        float inv = 1.0f / (e0 + e1);
        float r0 = 0.7f * e0 * inv, r1 = 0.3f * e1 * inv;
        g_w[48] = r0 / (r0 + r1);
    }
    __syncwarp();
    float alpha = g_w[48];
    float beta  = 1.0f - alpha;
    if (lane < 24) {
        float acc = sm[OFF_FUSB + lane];
        #pragma unroll
        for (int j = 0; j < 24; j++) acc = fmaf(sm[OFF_FUSW + lane * 36 + j], h_w[j] * alpha, acc);
        #pragma unroll
        for (int j = 0; j < 12; j++) acc = fmaf(sm[OFF_FUSW + lane * 36 + 24 + j], sa_s[j] * beta, acc);
        g_w[lane] = fmaxf(acc, 0.0f);
    }
    __syncwarp();
    if (lane < 12) {
        float acc = sm[OFF_CB1 + lane];
        #pragma unroll
        for (int o = 0; o < 24; o++) acc = fmaf(sm[OFF_CW1 + lane * 24 + o], g_w[o], acc);
        g_w[64 + lane] = fmaxf(acc, 0.0f);
    }
    __syncwarp();
    if (lane < 5) {
        float acc = sm[OFF_CB2 + lane];
        #pragma unroll
        for (int i = 0; i < 12; i++) acc = fmaf(sm[OFF_CW2 + lane * 12 + i], g_w[64 + i], acc);
        out[(size_t)sg * 5 + lane] = acc;
    }
}

// =====================================================================
extern "C" void kernel_launch(void* const* d_in, const int* in_sizes, int n_in,
                              void* d_out, int out_size) {
    (void)in_sizes; (void)n_in; (void)out_size;
    cudaFuncSetAttribute(fused_kernel,
                         cudaFuncAttributeMaxDynamicSharedMemorySize, SMEM_BYTES);
    fused_kernel<<<BTOT / SAMP, THREADS, SMEM_BYTES>>>(
        (const float*)d_in[0],
        (const float*)d_in[1],  (const float*)d_in[2],
        (const float*)d_in[3],  (const float*)d_in[4],
        (const float*)d_in[5],  (const float*)d_in[6],
        (const float*)d_in[7],  (const float*)d_in[8],
        (const float*)d_in[9],  (const float*)d_in[10],
        (const float*)d_in[11], (const float*)d_in[12],
        (const float*)d_in[13], (const float*)d_in[14],
        (const float*)d_in[15], (const float*)d_in[16],
        (const float*)d_in[17], (const float*)d_in[18],
        (const float*)d_in[19], (const float*)d_in[20],
        (const float*)d_in[21], (const float*)d_in[22],
        (const float*)d_in[23], (const float*)d_in[24],
        (const float*)d_in[25], (const float*)d_in[26],
        (float*)d_out);
}